// round 10
// baseline (speedup 1.0000x reference)
#include <cuda_runtime.h>
#include <math.h>

#define NN 100000
#define NE 3200000
#define HID 16
#define ES  (NE / 4)             // 800000 edge stripe
#define GG  (NN / 16)            // gemm blocks (6250, exact)
#define GE  ((NE + 255) / 256)   // deg blocks (12500)

// Scratch (static device globals — zero-initialized at load)
__device__ float d_deg [NN];     // zero at load; re-zeroed by k_dinv_scale
__device__ float d_dinv[NN];
__device__ float d_g  [NN * HID];
__device__ float d_agg[NN * HID];

// ---- fused: [blocks 0..GG) u = x@W1 (unscaled) + zero agg;
//             [blocks GG..GG+GE) weighted in-degree atomics ------------------
// gemm phase: x read DIRECTLY from global (broadcast LDG.128 across the 16
// channel lanes; sequential kk reuse the L1 line). Only W staged in smem.
#define WPAD 132
__global__ void k_gemm1_deg(const float* __restrict__ x,
                            const float* __restrict__ W1,
                            const int* __restrict__ col,
                            const float* __restrict__ ew) {
    if (blockIdx.x >= GG) {
        int e = (blockIdx.x - GG) * 256 + threadIdx.x;
        if (e < NE) atomicAdd(&d_deg[col[e]], ew[e]);
        return;
    }
    __shared__ float Wt[HID * WPAD];   // Wt[c][k]
    int t = threadIdx.x;
    for (int j = t; j < 128 * HID; j += 256) {
        int k = j >> 4, c = j & 15;
        Wt[c * WPAD + k] = W1[j];
    }
    __syncthreads();

    int node = blockIdx.x * 16 + (t >> 4);   // NN % 16 == 0: always valid
    int c    = t & 15;

    const float4* xr   = (const float4*)x + (size_t)node * 32;
    const float*  wrow = Wt + c * WPAD;
    float acc = 0.0f;
#pragma unroll
    for (int kk = 0; kk < 32; kk++) {
        float4 xv = __ldg(xr + kk);                   // broadcast across 16 lanes
        float4 wv = *(const float4*)(wrow + kk * 4);  // 2-phase LDS.128 (floor)
        acc += xv.x * wv.x + xv.y * wv.y + xv.z * wv.z + xv.w * wv.w;
    }
    int idx = node * HID + c;
    d_g[idx]   = acc;                                 // unscaled
    d_agg[idx] = 0.0f;                                // zero for edge pass 1
}

// ---- dinv = rsqrt(1+deg); g *= dinv; reset deg ------------------------------
__global__ void k_dinv_scale() {
    int idx = blockIdx.x * blockDim.x + threadIdx.x;
    if (idx >= NN * HID) return;
    int node = idx >> 4;
    float dv = rsqrtf(1.0f + d_deg[node]);   // broadcast load
    d_g[idx] *= dv;
    if ((idx & 15) == 0) {
        d_dinv[node] = dv;
        d_deg[node]  = 0.0f;                 // reset for next replay
    }
}

// ---- edge scatter: agg[col] += ew * g[row] ---------------------------------
// 4 threads per edge-slot, 4 striped edges per thread (MLP=4 gathers),
// fire-and-forget vector REDs. (Measured L1-wavefront floor ~50us; unchanged.)
__global__ void k_edges(const int* __restrict__ row,
                        const int* __restrict__ col,
                        const float* __restrict__ ew) {
    int idx = blockIdx.x * 256 + threadIdx.x;
    int e0 = idx >> 2;
    int q  = idx & 3;
    if (e0 >= ES) return;

    int    r[4], d[4];
    float  w[4];
    float4 g[4];
#pragma unroll
    for (int j = 0; j < 4; j++) {
        int e = e0 + j * ES;
        r[j] = __ldg(row + e);
        d[j] = __ldg(col + e);
        w[j] = __ldg(ew  + e);
    }
#pragma unroll
    for (int j = 0; j < 4; j++)
        g[j] = __ldg((const float4*)d_g + r[j] * 4 + q);
#pragma unroll
    for (int j = 0; j < 4; j++) {
        float* p = d_agg + d[j] * HID + q * 4;
        asm volatile("red.global.add.v4.f32 [%0], {%1,%2,%3,%4};"
                     :: "l"(p), "f"(w[j] * g[j].x), "f"(w[j] * g[j].y),
                        "f"(w[j] * g[j].z), "f"(w[j] * g[j].w)
                     : "memory");
    }
}

// ---- fused: h = relu(dinv*(agg+g)+b1);  g = dinv*(h @ W2); zero agg --------
// h lives in a 16-lane segment; W2 contraction done via shfl (no smem h).
__global__ void k_combine_gemm2(const float* __restrict__ b1,
                                const float* __restrict__ W2) {
    __shared__ float W2s[HID * HID];
    int t = threadIdx.x;
    if (t < HID * HID) W2s[t] = W2[t];
    __syncthreads();

    int node = blockIdx.x * 16 + (t >> 4);   // NN % 16 == 0: always valid
    int c    = t & 15;
    int idx  = node * HID + c;
    float dv = d_dinv[node];
    float v  = fmaxf(dv * (d_agg[idx] + d_g[idx]) + b1[c], 0.0f);

    float acc = 0.0f;
#pragma unroll
    for (int k = 0; k < HID; k++) {
        float hk = __shfl_sync(0xffffffffu, v, k, 16);
        acc += hk * W2s[k * HID + c];
    }
    d_g[idx]   = dv * acc;
    d_agg[idx] = 0.0f;                       // zero for edge pass 2
}

// ---- final: out = relu(dinv*(agg+g)+b2) @ Wout + bout ----------------------
__global__ void k_out(const float* __restrict__ b2,
                      const float* __restrict__ Wout,
                      const float* __restrict__ bout,
                      float* __restrict__ out) {
    int i = blockIdx.x * blockDim.x + threadIdx.x;
    if (i >= NN) return;
    float dv = d_dinv[i];
    const float4* a4 = (const float4*)d_agg + i * 4;
    const float4* g4 = (const float4*)d_g   + i * 4;
    float s = 0.0f;
#pragma unroll
    for (int q = 0; q < 4; q++) {
        float4 a = a4[q], g = g4[q];
        int c = q * 4;
        s += fmaxf(dv * (a.x + g.x) + __ldg(b2 + c + 0), 0.0f) * __ldg(Wout + c + 0);
        s += fmaxf(dv * (a.y + g.y) + __ldg(b2 + c + 1), 0.0f) * __ldg(Wout + c + 1);
        s += fmaxf(dv * (a.z + g.z) + __ldg(b2 + c + 2), 0.0f) * __ldg(Wout + c + 2);
        s += fmaxf(dv * (a.w + g.w) + __ldg(b2 + c + 3), 0.0f) * __ldg(Wout + c + 3);
    }
    out[i] = s + __ldg(bout);
}

extern "C" void kernel_launch(void* const* d_in, const int* in_sizes, int n_in,
                              void* d_out, int out_size) {
    const float* x    = (const float*)d_in[0];
    const int*   ei   = (const int*)d_in[1];   // [2, NE] int32
    const float* ea   = (const float*)d_in[2];
    const float* W1   = (const float*)d_in[5];
    const float* b1   = (const float*)d_in[6];
    const float* W2   = (const float*)d_in[7];
    const float* b2   = (const float*)d_in[8];
    const float* Wout = (const float*)d_in[9];
    const float* bout = (const float*)d_in[10];
    float*       out  = (float*)d_out;

    const int* row = ei;
    const int* col = ei + NE;

    const int T = 256;
    int gN  = (NN + T - 1) / T;
    int gNC = (NN * HID + T - 1) / T;
    int gE4 = (ES * 4 + T - 1) / T;

    // fused: gemm1 (unscaled, no x staging) + degree atomics, co-scheduled
    k_gemm1_deg<<<GG + GE, T>>>(x, W1, col, ea);
    k_dinv_scale<<<gNC, T>>>();            // dinv, scale g, reset deg

    // layer 1
    k_edges<<<gE4, T>>>(row, col, ea);
    k_combine_gemm2<<<GG, T>>>(b1, W2);    // also zeroes agg

    // layer 2
    k_edges<<<gE4, T>>>(row, col, ea);

    // fused combine + output projection
    k_out<<<gN, T>>>(b2, Wout, bout, out);
}

// round 11
// speedup vs baseline: 1.0023x; 1.0023x over previous
#include <cuda_runtime.h>
#include <cuda_fp16.h>
#include <math.h>

#define NN 100000
#define NE 3200000
#define HID 16
#define ES  (NE / 4)             // 800000 edge stripe
#define GG  (NN / 16)            // gemm blocks (6250, exact)
#define GE  ((NE + 255) / 256)   // deg blocks (12500)

// Scratch (static device globals — zero-initialized at load)
__device__ float  d_deg [NN];    // zero at load; re-zeroed by k_dinv_scale
__device__ float  d_dinv[NN];
__device__ float  d_u  [NN * HID];   // unscaled x@W1 (fp32 staging)
__device__ __half d_gh [NN * HID];   // dinv-scaled features, fp16 (32B/node)
__device__ float  d_agg[NN * HID];   // fp32 accumulation

// ---- fused: [blocks 0..GG) u = x@W1 (unscaled) + zero agg;
//             [blocks GG..GG+GE) weighted in-degree atomics ------------------
#define WPAD 132
__global__ void k_gemm1_deg(const float* __restrict__ x,
                            const float* __restrict__ W1,
                            const int* __restrict__ col,
                            const float* __restrict__ ew) {
    if (blockIdx.x >= GG) {
        int e = (blockIdx.x - GG) * 256 + threadIdx.x;
        if (e < NE) atomicAdd(&d_deg[col[e]], ew[e]);
        return;
    }
    __shared__ float Wt[HID * WPAD];   // Wt[c][k], WPAD=132: conflict-free LDS.128
    int t = threadIdx.x;
    for (int j = t; j < 128 * HID; j += 256) {
        int k = j >> 4, c = j & 15;
        Wt[c * WPAD + k] = W1[j];
    }
    __syncthreads();

    int node = blockIdx.x * 16 + (t >> 4);   // NN % 16 == 0
    int c    = t & 15;

    const float4* xr   = (const float4*)x + (size_t)node * 32;
    const float*  wrow = Wt + c * WPAD;
    float acc = 0.0f;
#pragma unroll
    for (int kk = 0; kk < 32; kk++) {
        float4 xv = __ldg(xr + kk);                   // broadcast across 16 lanes
        float4 wv = *(const float4*)(wrow + kk * 4);
        acc += xv.x * wv.x + xv.y * wv.y + xv.z * wv.z + xv.w * wv.w;
    }
    int idx = node * HID + c;
    d_u[idx]   = acc;                                 // unscaled fp32
    d_agg[idx] = 0.0f;                                // zero for edge pass 1
}

// ---- dinv = rsqrt(1+deg); gh = half(dinv*u); reset deg ----------------------
__global__ void k_dinv_scale() {
    int idx = blockIdx.x * blockDim.x + threadIdx.x;
    if (idx >= NN * HID) return;
    int node = idx >> 4;
    float dv = rsqrtf(1.0f + d_deg[node]);
    d_gh[idx] = __float2half(d_u[idx] * dv);
    if ((idx & 15) == 0) {
        d_dinv[node] = dv;
        d_deg[node]  = 0.0f;                 // reset for next replay
    }
}

// ---- edge scatter: agg[col] += ew * gh[row] ---------------------------------
// 4 threads/edge-slot, 4 striped edges/thread. fp16 gather (8B/lane, 32B/edge),
// fp32 math, fire-and-forget vector REDs.
__global__ void k_edges(const int* __restrict__ row,
                        const int* __restrict__ col,
                        const float* __restrict__ ew) {
    int idx = blockIdx.x * 256 + threadIdx.x;
    int e0 = idx >> 2;
    int q  = idx & 3;
    if (e0 >= ES) return;

    int   r[4], d[4];
    float w[4];
    uint2 gv[4];
#pragma unroll
    for (int j = 0; j < 4; j++) {
        int e = e0 + j * ES;
        r[j] = __ldg(row + e);
        d[j] = __ldg(col + e);
        w[j] = __ldg(ew  + e);
    }
#pragma unroll
    for (int j = 0; j < 4; j++)
        gv[j] = __ldg((const uint2*)d_gh + r[j] * 4 + q);   // 4 halves
#pragma unroll
    for (int j = 0; j < 4; j++) {
        float2 f01 = __half22float2(*(const __half2*)&gv[j].x);
        float2 f23 = __half22float2(*(const __half2*)&gv[j].y);
        float* p = d_agg + d[j] * HID + q * 4;
        asm volatile("red.global.add.v4.f32 [%0], {%1,%2,%3,%4};"
                     :: "l"(p), "f"(w[j] * f01.x), "f"(w[j] * f01.y),
                        "f"(w[j] * f23.x), "f"(w[j] * f23.y)
                     : "memory");
    }
}

// ---- fused: h = relu(dinv*(agg+g)+b1);  gh = half(dinv*(h @ W2)); zero agg --
__global__ void k_combine_gemm2(const float* __restrict__ b1,
                                const float* __restrict__ W2) {
    __shared__ float W2s[HID * HID];
    int t = threadIdx.x;
    if (t < HID * HID) W2s[t] = W2[t];
    __syncthreads();

    int node = blockIdx.x * 16 + (t >> 4);   // NN % 16 == 0
    int c    = t & 15;
    int idx  = node * HID + c;
    float dv = d_dinv[node];
    float g  = __half2float(d_gh[idx]);
    float v  = fmaxf(dv * (d_agg[idx] + g) + b1[c], 0.0f);

    float acc = 0.0f;
#pragma unroll
    for (int k = 0; k < HID; k++) {
        float hk = __shfl_sync(0xffffffffu, v, k, 16);
        acc += hk * W2s[k * HID + c];
    }
    d_gh[idx]  = __float2half(dv * acc);
    d_agg[idx] = 0.0f;                       // zero for edge pass 2
}

// ---- final: out = relu(dinv*(agg+g)+b2) @ Wout + bout -----------------------
__global__ void k_out(const float* __restrict__ b2,
                      const float* __restrict__ Wout,
                      const float* __restrict__ bout,
                      float* __restrict__ out) {
    int i = blockIdx.x * blockDim.x + threadIdx.x;
    if (i >= NN) return;
    float dv = d_dinv[i];
    const float4* a4 = (const float4*)d_agg + i * 4;
    const uint2*  g4 = (const uint2*)d_gh + i * 4;
    float s = 0.0f;
#pragma unroll
    for (int q = 0; q < 4; q++) {
        float4 a = a4[q];
        uint2 gb = g4[q];
        float2 g01 = __half22float2(*(const __half2*)&gb.x);
        float2 g23 = __half22float2(*(const __half2*)&gb.y);
        int c = q * 4;
        s += fmaxf(dv * (a.x + g01.x) + __ldg(b2 + c + 0), 0.0f) * __ldg(Wout + c + 0);
        s += fmaxf(dv * (a.y + g01.y) + __ldg(b2 + c + 1), 0.0f) * __ldg(Wout + c + 1);
        s += fmaxf(dv * (a.z + g23.x) + __ldg(b2 + c + 2), 0.0f) * __ldg(Wout + c + 2);
        s += fmaxf(dv * (a.w + g23.y) + __ldg(b2 + c + 3), 0.0f) * __ldg(Wout + c + 3);
    }
    out[i] = s + __ldg(bout);
}

extern "C" void kernel_launch(void* const* d_in, const int* in_sizes, int n_in,
                              void* d_out, int out_size) {
    const float* x    = (const float*)d_in[0];
    const int*   ei   = (const int*)d_in[1];   // [2, NE] int32
    const float* ea   = (const float*)d_in[2];
    const float* W1   = (const float*)d_in[5];
    const float* b1   = (const float*)d_in[6];
    const float* W2   = (const float*)d_in[7];
    const float* b2   = (const float*)d_in[8];
    const float* Wout = (const float*)d_in[9];
    const float* bout = (const float*)d_in[10];
    float*       out  = (float*)d_out;

    const int* row = ei;
    const int* col = ei + NE;

    const int T = 256;
    int gN  = (NN + T - 1) / T;
    int gNC = (NN * HID + T - 1) / T;
    int gE4 = (ES * 4 + T - 1) / T;

    // fused: gemm1 (unscaled) + degree atomics, co-scheduled
    k_gemm1_deg<<<GG + GE, T>>>(x, W1, col, ea);
    k_dinv_scale<<<gNC, T>>>();            // dinv, fp16 scale, reset deg

    // layer 1
    k_edges<<<gE4, T>>>(row, col, ea);
    k_combine_gemm2<<<GG, T>>>(b1, W2);    // also zeroes agg

    // layer 2
    k_edges<<<gE4, T>>>(row, col, ea);

    // fused combine + output projection
    k_out<<<gN, T>>>(b2, Wout, bout, out);
}

// round 12
// speedup vs baseline: 1.1420x; 1.1394x over previous
#include <cuda_runtime.h>
#include <cuda_fp16.h>
#include <math.h>

#define NN 100000
#define NE 3200000
#define HID 16
#define ES  (NE / 4)             // 800000 edge stripe
#define GG  ((NN + 63) / 64)     // gemm blocks (1563, 64 nodes each)
#define GE  ((NE + 255) / 256)   // deg blocks (12500)
#define XPITCH 132               // padded x row pitch (words); 132%32=4

// Scratch (static device globals — zero-initialized at load)
__device__ float  d_deg [NN];    // zero at load; re-zeroed by k_dinv_scale
__device__ float  d_dinv[NN];
__device__ __half d_u  [NN * HID];   // unscaled x@W1, fp16
__device__ __half d_gh [NN * HID];   // dinv-scaled features, fp16 (32B/node)
__device__ float  d_agg[NN * HID];   // fp32 accumulation

// ---- fused: [blocks 0..GG) u = x@W1 (unscaled, 4 nodes/thread) + zero agg;
//             [blocks GG..GG+GE) weighted in-degree atomics ------------------
#define WPAD 132
__global__ void k_gemm1_deg(const float* __restrict__ x,
                            const float* __restrict__ W1,
                            const int* __restrict__ col,
                            const float* __restrict__ ew) {
    if (blockIdx.x >= GG) {
        int e = (blockIdx.x - GG) * 256 + threadIdx.x;
        if (e < NE) atomicAdd(&d_deg[col[e]], ew[e]);
        return;
    }
    __shared__ float xs[64 * XPITCH];  // 33 KB, padded rows (conflict-free)
    __shared__ float Wt[HID * WPAD];   // 8.25 KB, Wt[c][k]
    int t = threadIdx.x;
    int base = blockIdx.x * 64;
    int nvalid = NN - base; if (nvalid > 64) nvalid = 64;

    // stage x rows: coalesced float4 reads, padded smem rows
    const float4* xg = (const float4*)x + (size_t)base * 32;
    for (int j = t; j < nvalid * 32; j += 256) {
        int n = j >> 5, k4 = j & 31;
        *(float4*)(xs + n * XPITCH + k4 * 4) = xg[j];
    }
    for (int j = t; j < 128 * HID; j += 256) {
        int k = j >> 4, c = j & 15;
        Wt[c * WPAD + k] = W1[j];
    }
    __syncthreads();

    int c  = t & 15;
    int ng = t >> 4;                   // node-group 0..15 (4 nodes each)
    int n0 = ng * 4;                   // local node base

    float acc0 = 0.f, acc1 = 0.f, acc2 = 0.f, acc3 = 0.f;
    const float* wrow = Wt + c * WPAD;
    const float* x0 = xs + (n0 + 0) * XPITCH;
    const float* x1 = xs + (n0 + 1) * XPITCH;
    const float* x2 = xs + (n0 + 2) * XPITCH;
    const float* x3 = xs + (n0 + 3) * XPITCH;
#pragma unroll
    for (int kk = 0; kk < 32; kk++) {
        float4 wv = *(const float4*)(wrow + kk * 4);
        float4 a  = *(const float4*)(x0 + kk * 4);
        float4 b  = *(const float4*)(x1 + kk * 4);
        float4 d  = *(const float4*)(x2 + kk * 4);
        float4 e  = *(const float4*)(x3 + kk * 4);
        acc0 += a.x*wv.x + a.y*wv.y + a.z*wv.z + a.w*wv.w;
        acc1 += b.x*wv.x + b.y*wv.y + b.z*wv.z + b.w*wv.w;
        acc2 += d.x*wv.x + d.y*wv.y + d.z*wv.z + d.w*wv.w;
        acc3 += e.x*wv.x + e.y*wv.y + e.z*wv.z + e.w*wv.w;
    }
    float accs[4] = {acc0, acc1, acc2, acc3};
#pragma unroll
    for (int m = 0; m < 4; m++) {
        int node = base + n0 + m;
        if (node < NN) {
            int idx = node * HID + c;
            d_u[idx]   = __float2half(accs[m]);
            d_agg[idx] = 0.0f;             // zero for edge pass 1
        }
    }
}

// ---- dinv = rsqrt(1+deg); gh = half(dinv*u); reset deg ----------------------
__global__ void k_dinv_scale() {
    int idx = blockIdx.x * blockDim.x + threadIdx.x;
    if (idx >= NN * HID) return;
    int node = idx >> 4;
    float dv = rsqrtf(1.0f + d_deg[node]);
    d_gh[idx] = __float2half(__half2float(d_u[idx]) * dv);
    if ((idx & 15) == 0) {
        d_dinv[node] = dv;
        d_deg[node]  = 0.0f;               // reset for next replay
    }
}

// ---- edge scatter: agg[col] += ew * gh[row] ---------------------------------
// 4 threads/edge-slot, 4 striped edges/thread. fp16 gather, fp32 REDs.
__global__ void k_edges(const int* __restrict__ row,
                        const int* __restrict__ col,
                        const float* __restrict__ ew) {
    int idx = blockIdx.x * 256 + threadIdx.x;
    int e0 = idx >> 2;
    int q  = idx & 3;
    if (e0 >= ES) return;

    int   r[4], d[4];
    float w[4];
    uint2 gv[4];
#pragma unroll
    for (int j = 0; j < 4; j++) {
        int e = e0 + j * ES;
        r[j] = __ldg(row + e);
        d[j] = __ldg(col + e);
        w[j] = __ldg(ew  + e);
    }
#pragma unroll
    for (int j = 0; j < 4; j++)
        gv[j] = __ldg((const uint2*)d_gh + r[j] * 4 + q);
#pragma unroll
    for (int j = 0; j < 4; j++) {
        float2 f01 = __half22float2(*(const __half2*)&gv[j].x);
        float2 f23 = __half22float2(*(const __half2*)&gv[j].y);
        float* p = d_agg + d[j] * HID + q * 4;
        asm volatile("red.global.add.v4.f32 [%0], {%1,%2,%3,%4};"
                     :: "l"(p), "f"(w[j] * f01.x), "f"(w[j] * f01.y),
                        "f"(w[j] * f23.x), "f"(w[j] * f23.y)
                     : "memory");
    }
}

// ---- fused: h = relu(dinv*(agg+g)+b1);  gh = half(dinv*(h @ W2)); zero agg --
__global__ void k_combine_gemm2(const float* __restrict__ b1,
                                const float* __restrict__ W2) {
    __shared__ float W2s[HID * HID];
    int t = threadIdx.x;
    if (t < HID * HID) W2s[t] = W2[t];
    __syncthreads();

    int node = blockIdx.x * 16 + (t >> 4);   // NN % 16 == 0
    int c    = t & 15;
    int idx  = node * HID + c;
    float dv = d_dinv[node];
    float g  = __half2float(d_gh[idx]);
    float v  = fmaxf(dv * (d_agg[idx] + g) + b1[c], 0.0f);

    float acc = 0.0f;
#pragma unroll
    for (int k = 0; k < HID; k++) {
        float hk = __shfl_sync(0xffffffffu, v, k, 16);
        acc += hk * W2s[k * HID + c];
    }
    d_gh[idx]  = __float2half(dv * acc);
    d_agg[idx] = 0.0f;                       // zero for edge pass 2
}

// ---- final: out = relu(dinv*(agg+g)+b2) @ Wout + bout -----------------------
__global__ void k_out(const float* __restrict__ b2,
                      const float* __restrict__ Wout,
                      const float* __restrict__ bout,
                      float* __restrict__ out) {
    int i = blockIdx.x * blockDim.x + threadIdx.x;
    if (i >= NN) return;
    float dv = d_dinv[i];
    const float4* a4 = (const float4*)d_agg + i * 4;
    const uint2*  g4 = (const uint2*)d_gh + i * 4;
    float s = 0.0f;
#pragma unroll
    for (int q = 0; q < 4; q++) {
        float4 a = a4[q];
        uint2 gb = g4[q];
        float2 g01 = __half22float2(*(const __half2*)&gb.x);
        float2 g23 = __half22float2(*(const __half2*)&gb.y);
        int c = q * 4;
        s += fmaxf(dv * (a.x + g01.x) + __ldg(b2 + c + 0), 0.0f) * __ldg(Wout + c + 0);
        s += fmaxf(dv * (a.y + g01.y) + __ldg(b2 + c + 1), 0.0f) * __ldg(Wout + c + 1);
        s += fmaxf(dv * (a.z + g23.x) + __ldg(b2 + c + 2), 0.0f) * __ldg(Wout + c + 2);
        s += fmaxf(dv * (a.w + g23.y) + __ldg(b2 + c + 3), 0.0f) * __ldg(Wout + c + 3);
    }
    out[i] = s + __ldg(bout);
}

extern "C" void kernel_launch(void* const* d_in, const int* in_sizes, int n_in,
                              void* d_out, int out_size) {
    const float* x    = (const float*)d_in[0];
    const int*   ei   = (const int*)d_in[1];   // [2, NE] int32
    const float* ea   = (const float*)d_in[2];
    const float* W1   = (const float*)d_in[5];
    const float* b1   = (const float*)d_in[6];
    const float* W2   = (const float*)d_in[7];
    const float* b2   = (const float*)d_in[8];
    const float* Wout = (const float*)d_in[9];
    const float* bout = (const float*)d_in[10];
    float*       out  = (float*)d_out;

    const int* row = ei;
    const int* col = ei + NE;

    const int T = 256;
    int gN  = (NN + T - 1) / T;
    int gNC = (NN * HID + T - 1) / T;
    int gE4 = (ES * 4 + T - 1) / T;
    int gC  = NN / 16;

    // fused: gemm1 (register-blocked, unscaled) + degree atomics, co-scheduled
    k_gemm1_deg<<<GG + GE, T>>>(x, W1, col, ea);
    k_dinv_scale<<<gNC, T>>>();            // dinv, fp16 scale, reset deg

    // layer 1
    k_edges<<<gE4, T>>>(row, col, ea);
    k_combine_gemm2<<<gC, T>>>(b1, W2);    // also zeroes agg

    // layer 2
    k_edges<<<gE4, T>>>(row, col, ea);

    // fused combine + output projection
    k_out<<<gN, T>>>(b2, Wout, bout, out);
}

// round 13
// speedup vs baseline: 1.1836x; 1.0365x over previous
#include <cuda_runtime.h>
#include <cuda_fp16.h>
#include <math.h>

#define NN 100000
#define NE 3200000
#define HID 16
#define ES  (NE / 4)             // 800000 edge stripe
#define GG  ((NN + 63) / 64)     // gemm tiles (1563, 64 nodes each)
#define GE  ((NE + 255) / 256)   // deg blocks (12500)
#define GT  (GG + GE)            // 14063 fused blocks
#define XPITCH 132               // padded x row pitch (words); 132%32=4

// Scratch (static device globals — zero-initialized at load)
__device__ float  d_deg [NN];    // zero at load; re-zeroed by k_dinv_scale
__device__ float  d_dinv[NN];
__device__ __half d_u  [NN * HID];   // unscaled x@W1, fp16
__device__ __half d_gh [NN * HID];   // dinv-scaled features, fp16 (32B/node)
__device__ float  d_agg[NN * HID];   // fp32 accumulation

// ---- fused: interleaved gemm tiles (every 9th block) + deg atomic blocks ----
// Interleaving keeps heavy gemm blocks and light atomic blocks co-resident in
// every wave instead of serializing the two phases.
#define WPAD 132
__global__ void k_gemm1_deg(const float* __restrict__ x,
                            const float* __restrict__ W1,
                            const int* __restrict__ col,
                            const float* __restrict__ ew) {
    int B = blockIdx.x;
    if (B % 9 != 0) {
        int db = B - B / 9 - 1;            // 0..GE-1
        int e = db * 256 + threadIdx.x;
        if (e < NE) atomicAdd(&d_deg[col[e]], ew[e]);
        return;
    }
    int gb = B / 9;                        // 0..GG-1
    __shared__ float xs[64 * XPITCH];      // 33 KB, padded rows
    __shared__ float Wt[HID * WPAD];       // Wt[c][k]
    int t = threadIdx.x;
    int base = gb * 64;
    int nvalid = NN - base; if (nvalid > 64) nvalid = 64;

    const float4* xg = (const float4*)x + (size_t)base * 32;
    for (int j = t; j < nvalid * 32; j += 256) {
        int n = j >> 5, k4 = j & 31;
        *(float4*)(xs + n * XPITCH + k4 * 4) = xg[j];
    }
    for (int j = t; j < 128 * HID; j += 256) {
        int k = j >> 4, c = j & 15;
        Wt[c * WPAD + k] = W1[j];
    }
    __syncthreads();

    int c  = t & 15;
    int n0 = (t >> 4) * 4;

    float acc0 = 0.f, acc1 = 0.f, acc2 = 0.f, acc3 = 0.f;
    const float* wrow = Wt + c * WPAD;
    const float* x0 = xs + (n0 + 0) * XPITCH;
    const float* x1 = xs + (n0 + 1) * XPITCH;
    const float* x2 = xs + (n0 + 2) * XPITCH;
    const float* x3 = xs + (n0 + 3) * XPITCH;
#pragma unroll
    for (int kk = 0; kk < 32; kk++) {
        float4 wv = *(const float4*)(wrow + kk * 4);
        float4 a  = *(const float4*)(x0 + kk * 4);
        float4 b  = *(const float4*)(x1 + kk * 4);
        float4 d  = *(const float4*)(x2 + kk * 4);
        float4 e  = *(const float4*)(x3 + kk * 4);
        acc0 += a.x*wv.x + a.y*wv.y + a.z*wv.z + a.w*wv.w;
        acc1 += b.x*wv.x + b.y*wv.y + b.z*wv.z + b.w*wv.w;
        acc2 += d.x*wv.x + d.y*wv.y + d.z*wv.z + d.w*wv.w;
        acc3 += e.x*wv.x + e.y*wv.y + e.z*wv.z + e.w*wv.w;
    }
    float accs[4] = {acc0, acc1, acc2, acc3};
#pragma unroll
    for (int m = 0; m < 4; m++) {
        int node = base + n0 + m;
        if (node < NN) {
            int idx = node * HID + c;
            d_u[idx]   = __float2half(accs[m]);
            d_agg[idx] = 0.0f;             // zero for edge pass 1
        }
    }
}

// ---- dinv = rsqrt(1+deg); gh = half(dinv*u); reset deg ----------------------
__global__ void k_dinv_scale() {
    int idx = blockIdx.x * blockDim.x + threadIdx.x;
    if (idx >= NN * HID) return;
    int node = idx >> 4;
    float dv = rsqrtf(1.0f + d_deg[node]);
    d_gh[idx] = __float2half(__half2float(d_u[idx]) * dv);
    if ((idx & 15) == 0) {
        d_dinv[node] = dv;
        d_deg[node]  = 0.0f;               // reset for next replay
    }
}

// ---- edge scatter: agg[col] += ew * gh[row] (UNCHANGED — noise control) -----
__global__ void k_edges(const int* __restrict__ row,
                        const int* __restrict__ col,
                        const float* __restrict__ ew) {
    int idx = blockIdx.x * 256 + threadIdx.x;
    int e0 = idx >> 2;
    int q  = idx & 3;
    if (e0 >= ES) return;

    int   r[4], d[4];
    float w[4];
    uint2 gv[4];
#pragma unroll
    for (int j = 0; j < 4; j++) {
        int e = e0 + j * ES;
        r[j] = __ldg(row + e);
        d[j] = __ldg(col + e);
        w[j] = __ldg(ew  + e);
    }
#pragma unroll
    for (int j = 0; j < 4; j++)
        gv[j] = __ldg((const uint2*)d_gh + r[j] * 4 + q);
#pragma unroll
    for (int j = 0; j < 4; j++) {
        float2 f01 = __half22float2(*(const __half2*)&gv[j].x);
        float2 f23 = __half22float2(*(const __half2*)&gv[j].y);
        float* p = d_agg + d[j] * HID + q * 4;
        asm volatile("red.global.add.v4.f32 [%0], {%1,%2,%3,%4};"
                     :: "l"(p), "f"(w[j] * f01.x), "f"(w[j] * f01.y),
                        "f"(w[j] * f23.x), "f"(w[j] * f23.y)
                     : "memory");
    }
}

// ---- fused: h = relu(dinv*(agg+g)+b1);  gh = half(dinv*(h @ W2)); zero agg --
// smem-h + transposed W2 (pitches 20/36): contraction = 8 LDS.128/thread,
// replacing the shfl-pipe-bound 16-SHFL chain.
#define HPITCH 20
#define W2PITCH 36
__global__ void k_combine_gemm2(const float* __restrict__ b1,
                                const float* __restrict__ W2) {
    __shared__ float hs[16 * HPITCH];
    __shared__ float W2t[HID * W2PITCH];   // W2t[c][k]
    int t = threadIdx.x;
    if (t < HID * HID) {
        int k = t >> 4, c = t & 15;
        W2t[c * W2PITCH + k] = W2[t];      // W2 is [k][c] row-major
    }

    int nloc = t >> 4;
    int node = blockIdx.x * 16 + nloc;     // NN % 16 == 0
    int c    = t & 15;
    int idx  = node * HID + c;
    float dv = d_dinv[node];
    float g  = __half2float(d_gh[idx]);
    hs[nloc * HPITCH + c] =
        fmaxf(dv * (d_agg[idx] + g) + __ldg(b1 + c), 0.0f);
    __syncthreads();

    float acc = 0.0f;
    const float* hrow = hs + nloc * HPITCH;
    const float* wrow = W2t + c * W2PITCH;
#pragma unroll
    for (int q = 0; q < 4; q++) {
        float4 hv = *(const float4*)(hrow + q * 4);   // broadcast, 1 phase
        float4 wv = *(const float4*)(wrow + q * 4);   // 2-phase floor
        acc += hv.x*wv.x + hv.y*wv.y + hv.z*wv.z + hv.w*wv.w;
    }
    d_gh[idx]  = __float2half(dv * acc);
    d_agg[idx] = 0.0f;                     // zero for edge pass 2
}

// ---- final: out = relu(dinv*(agg+g)+b2) @ Wout + bout -----------------------
__global__ void k_out(const float* __restrict__ b2,
                      const float* __restrict__ Wout,
                      const float* __restrict__ bout,
                      float* __restrict__ out) {
    int i = blockIdx.x * blockDim.x + threadIdx.x;
    if (i >= NN) return;
    float dv = d_dinv[i];
    const float4* a4 = (const float4*)d_agg + i * 4;
    const uint2*  g4 = (const uint2*)d_gh + i * 4;
    float s = 0.0f;
#pragma unroll
    for (int q = 0; q < 4; q++) {
        float4 a = a4[q];
        uint2 gb = g4[q];
        float2 g01 = __half22float2(*(const __half2*)&gb.x);
        float2 g23 = __half22float2(*(const __half2*)&gb.y);
        int c = q * 4;
        s += fmaxf(dv * (a.x + g01.x) + __ldg(b2 + c + 0), 0.0f) * __ldg(Wout + c + 0);
        s += fmaxf(dv * (a.y + g01.y) + __ldg(b2 + c + 1), 0.0f) * __ldg(Wout + c + 1);
        s += fmaxf(dv * (a.z + g23.x) + __ldg(b2 + c + 2), 0.0f) * __ldg(Wout + c + 2);
        s += fmaxf(dv * (a.w + g23.y) + __ldg(b2 + c + 3), 0.0f) * __ldg(Wout + c + 3);
    }
    out[i] = s + __ldg(bout);
}

extern "C" void kernel_launch(void* const* d_in, const int* in_sizes, int n_in,
                              void* d_out, int out_size) {
    const float* x    = (const float*)d_in[0];
    const int*   ei   = (const int*)d_in[1];   // [2, NE] int32
    const float* ea   = (const float*)d_in[2];
    const float* W1   = (const float*)d_in[5];
    const float* b1   = (const float*)d_in[6];
    const float* W2   = (const float*)d_in[7];
    const float* b2   = (const float*)d_in[8];
    const float* Wout = (const float*)d_in[9];
    const float* bout = (const float*)d_in[10];
    float*       out  = (float*)d_out;

    const int* row = ei;
    const int* col = ei + NE;

    const int T = 256;
    int gN  = (NN + T - 1) / T;
    int gNC = (NN * HID + T - 1) / T;
    int gE4 = (ES * 4 + T - 1) / T;
    int gC  = NN / 16;

    // fused: interleaved gemm1 (unscaled) + degree atomics
    k_gemm1_deg<<<GT, T>>>(x, W1, col, ea);
    k_dinv_scale<<<gNC, T>>>();            // dinv, fp16 scale, reset deg

    // layer 1
    k_edges<<<gE4, T>>>(row, col, ea);
    k_combine_gemm2<<<gC, T>>>(b1, W2);    // also zeroes agg

    // layer 2
    k_edges<<<gE4, T>>>(row, col, ea);

    // fused combine + output projection
    k_out<<<gN, T>>>(b2, Wout, bout, out);
}